// round 13
// baseline (speedup 1.0000x reference)
#include <cuda_runtime.h>
#include <cuda_bf16.h>
#include <cstdint>

#define DFEAT 256
#define NCOLS 512
#define MAXN  100000

// Scratch: P = [u | v] per node, bf16, 16B-aligned (uint4 reads).
// g_Hb = h converted to bf16 [M x 256]. g_W2 = W1 rearranged, k-pair interleaved.
__device__ __align__(16) __nv_bfloat16 g_P[(size_t)MAXN * NCOLS];
__device__ __align__(16) __nv_bfloat16 g_Hb[(size_t)MAXN * DFEAT];
__device__ __align__(16) __nv_bfloat16 g_W2[(DFEAT / 2) * NCOLS * 2];

// Wcat[k][j] = W1[k][j] (j<256) | W1[256+k][j-256]; stored pair-interleaved bf16.
__global__ void prep_w(const float* __restrict__ W1) {
    int idx = blockIdx.x * blockDim.x + threadIdx.x;
    if (idx >= NCOLS * DFEAT) return;
    int j = idx >> 8;          // output col 0..511
    int k = idx & 255;         // input  dim 0..255
    float w = (j < DFEAT) ? W1[k * DFEAT + j]
                          : W1[(DFEAT + k) * DFEAT + (j - DFEAT)];
    g_W2[(size_t)(k >> 1) * (NCOLS * 2) + j * 2 + (k & 1)] = __float2bfloat16(w);
}

// h (fp32) -> g_Hb (bf16), 8 elements per thread, pure streaming.
__global__ void prep_h(const float* __restrict__ h, int M) {
    size_t i8 = (size_t)(blockIdx.x * blockDim.x + threadIdx.x);
    size_t total = (size_t)M * DFEAT / 8;
    if (i8 >= total) return;
    const float4* src = (const float4*)h + i8 * 2;
    float4 f0 = src[0], f1 = src[1];
    uint4 o;
    asm("cvt.rn.bf16x2.f32 %0, %1, %2;" : "=r"(o.x) : "f"(f0.y), "f"(f0.x));
    asm("cvt.rn.bf16x2.f32 %0, %1, %2;" : "=r"(o.y) : "f"(f0.w), "f"(f0.z));
    asm("cvt.rn.bf16x2.f32 %0, %1, %2;" : "=r"(o.z) : "f"(f1.y), "f"(f1.x));
    asm("cvt.rn.bf16x2.f32 %0, %1, %2;" : "=r"(o.w) : "f"(f1.w), "f"(f1.z));
    ((uint4*)g_Hb)[i8] = o;
}

// ----- bf16 m16n8k16 GEMM, 3-stage cp.async, 2 CTAs/SM, bf16 A path (R12) -----
#define BM 128
#define BN 128
#define BK 32
#define ABST 40                    // A row stride in bf16 (80B) - conflict-free LDS.32
#define BSTR2 136                  // B row stride in uint32 (544B)
#define A_STAGE_H (BM * ABST)      // bf16 units per A stage
#define B_STAGE (BK / 2 * BSTR2)   // uint32 words per B stage
#define NSTAGE 3
#define SMEM_BYTES (NSTAGE * (A_STAGE_H * 2 + B_STAGE * 4))   // 56832 B

__device__ __forceinline__ void cp16(void* dst_s, const void* src_g, bool pred) {
    uint32_t d = (uint32_t)__cvta_generic_to_shared(dst_s);
    int sz = pred ? 16 : 0;   // 0 => zero-fill
    asm volatile("cp.async.ca.shared.global [%0], [%1], 16, %2;"
                 :: "r"(d), "l"(src_g), "r"(sz));
}

__global__ __launch_bounds__(256, 2) void gemm_bf16(int M) {
    extern __shared__ __align__(16) char smem[];
    __nv_bfloat16* As = (__nv_bfloat16*)smem;                      // [NSTAGE][A_STAGE_H]
    uint32_t*      Bs = (uint32_t*)(smem + NSTAGE * A_STAGE_H * 2);// [NSTAGE][B_STAGE]

    int tid  = threadIdx.x;
    int lane = tid & 31, warp = tid >> 5;
    int wm = (warp >> 2) * 64;         // warp grid 2(m) x 4(n), warp tile 64x32
    int wn = (warp & 3) * 32;
    int g  = lane >> 2, tg = lane & 3;
    int rowBase = blockIdx.y * BM;
    int nBase   = blockIdx.x * BN;

    float c[4][4][4];
    #pragma unroll
    for (int i = 0; i < 4; i++)
        #pragma unroll
        for (int j = 0; j < 4; j++)
            #pragma unroll
            for (int q = 0; q < 4; q++) c[i][j][q] = 0.f;

    // A-load mapping: 128 rows x 64B = 512 x 16B slots, 2/thread
    int ar[2], ac[2];
    #pragma unroll
    for (int i = 0; i < 2; i++) {
        int idx = tid + 256 * i;
        ar[i] = idx >> 2;           // row 0..127
        ac[i] = (idx & 3) << 3;     // col 0..24 step 8 (bf16 units)
    }
    // B-load mapping: 512 x 16B slots, 2/thread (16 rows x 128 uint32)
    int br[2], bc[2];
    #pragma unroll
    for (int i = 0; i < 2; i++) {
        int idx = tid + 256 * i;
        br[i] = idx >> 5;           // k2 row 0..15
        bc[i] = (idx & 31) << 2;    // word col 0..124 step 4
    }

    auto load_stage = [&](int st, int k0) {
        __nv_bfloat16* a_s = As + st * A_STAGE_H;
        uint32_t*      b_s = Bs + st * B_STAGE;
        #pragma unroll
        for (int i = 0; i < 2; i++) {
            int grow = rowBase + ar[i];
            cp16(a_s + ar[i] * ABST + ac[i],
                 g_Hb + (size_t)grow * DFEAT + k0 + ac[i], grow < M);
        }
        int k2base = k0 >> 1;
        #pragma unroll
        for (int i = 0; i < 2; i++) {
            cp16(b_s + br[i] * BSTR2 + bc[i],
                 g_W2 + (size_t)(k2base + br[i]) * (NCOLS * 2) + nBase * 2 + bc[i] * 2,
                 true);
        }
        asm volatile("cp.async.commit_group;");
    };

    load_stage(0, 0);
    load_stage(1, BK);

    for (int ck = 0; ck < DFEAT / BK; ck++) {          // 8 chunks
        if (ck + 1 < DFEAT / BK) asm volatile("cp.async.wait_group 1;");
        else                     asm volatile("cp.async.wait_group 0;");
        __syncthreads();

        const __nv_bfloat16* a_s = As + (ck % NSTAGE) * A_STAGE_H;
        const uint32_t*      b_s = Bs + (ck % NSTAGE) * B_STAGE;

        #pragma unroll
        for (int kk = 0; kk < BK; kk += 16) {
            // A frags (m16n8k16): a0 (g,2tg) a1 (g+8,2tg) a2 (g,2tg+8) a3 (g+8,2tg+8)
            uint32_t a[4][4];
            #pragma unroll
            for (int mt = 0; mt < 4; mt++) {
                const __nv_bfloat16* ap = a_s + (wm + mt * 16) * ABST + kk + 2 * tg;
                a[mt][0] = *(const uint32_t*)(ap + g * ABST);
                a[mt][1] = *(const uint32_t*)(ap + (g + 8) * ABST);
                a[mt][2] = *(const uint32_t*)(ap + g * ABST + 8);
                a[mt][3] = *(const uint32_t*)(ap + (g + 8) * ABST + 8);
            }
            // B frags: b0 = pair row (kk/2 + tg), b1 = pair row (kk/2 + tg + 4), col n
            uint32_t b[4][2];
            #pragma unroll
            for (int nt = 0; nt < 4; nt++) {
                const uint32_t* bp = b_s + (kk >> 1) * BSTR2 + wn + nt * 8 + g;
                b[nt][0] = bp[tg * BSTR2];
                b[nt][1] = bp[(tg + 4) * BSTR2];
            }
            #pragma unroll
            for (int mt = 0; mt < 4; mt++)
                #pragma unroll
                for (int nt = 0; nt < 4; nt++) {
                    asm volatile(
                        "mma.sync.aligned.m16n8k16.row.col.f32.bf16.bf16.f32 "
                        "{%0,%1,%2,%3}, {%4,%5,%6,%7}, {%8,%9}, {%0,%1,%2,%3};"
                        : "+f"(c[mt][nt][0]), "+f"(c[mt][nt][1]),
                          "+f"(c[mt][nt][2]), "+f"(c[mt][nt][3])
                        : "r"(a[mt][0]), "r"(a[mt][1]), "r"(a[mt][2]), "r"(a[mt][3]),
                          "r"(b[nt][0]), "r"(b[nt][1]));
                }
        }
        __syncthreads();

        if (ck + 2 < DFEAT / BK) load_stage((ck + 2) % NSTAGE, (ck + 2) * BK);
    }

    // Epilogue -> bf16 P. C frag: c0 (g,2tg) c1 (g,2tg+1) c2 (g+8,2tg) c3 (g+8,2tg+1)
    #pragma unroll
    for (int mt = 0; mt < 4; mt++) {
        int row0 = rowBase + wm + mt * 16 + g;
        #pragma unroll
        for (int nt = 0; nt < 4; nt++) {
            int col = nBase + wn + nt * 8 + 2 * tg;
            if (row0 < M)
                *(__nv_bfloat162*)(g_P + (size_t)row0 * NCOLS + col) =
                    __float22bfloat162_rn(make_float2(c[mt][nt][0], c[mt][nt][1]));
            if (row0 + 8 < M)
                *(__nv_bfloat162*)(g_P + (size_t)(row0 + 8) * NCOLS + col) =
                    __float22bfloat162_rn(make_float2(c[mt][nt][2], c[mt][nt][3]));
        }
    }
}

// ------------- edge pass: warp/edge, 2 in flight, bf16x2 SIMD math -----------
__device__ __forceinline__ float edge_dot2(uint4 uu, uint4 vv,
                                           const uint32_t* bb2, const float* ww) {
    float acc = 0.f;
    const uint32_t* up = &uu.x;
    const uint32_t* vp = &vv.x;
    #pragma unroll
    for (int q = 0; q < 4; q++) {
        uint32_t t;
        asm("add.rn.bf16x2 %0, %1, %2;" : "=r"(t) : "r"(up[q]), "r"(vp[q]));
        asm("add.rn.bf16x2 %0, %1, %2;" : "=r"(t) : "r"(t), "r"(bb2[q]));
        asm("max.bf16x2 %0, %1, %2;"    : "=r"(t) : "r"(t), "r"(0u));  // relu
        float lo = __uint_as_float(t << 16);          // bf16 -> fp32 bit placement
        float hi = __uint_as_float(t & 0xffff0000u);
        acc = fmaf(lo, ww[2 * q], acc);
        acc = fmaf(hi, ww[2 * q + 1], acc);
    }
    return acc;
}

__global__ __launch_bounds__(256) void edge_mlp(
        const int* __restrict__ src, const int* __restrict__ dst,
        const float* __restrict__ b1, const float* __restrict__ W2,
        const float* __restrict__ b2, float* __restrict__ out, int E) {
    int tid = threadIdx.x;
    int lane = tid & 31;
    int gwarp = blockIdx.x * 8 + (tid >> 5);
    int nwarps = gridDim.x * 8;

    // per-lane slice j = lane*8..lane*8+7: bias packed bf16x2, W2 kept fp32
    uint32_t bb2[4];
    float ww[8];
    #pragma unroll
    for (int i = 0; i < 4; i++) {
        float blo = __ldg(b1 + lane * 8 + 2 * i);
        float bhi = __ldg(b1 + lane * 8 + 2 * i + 1);
        asm("cvt.rn.bf16x2.f32 %0, %1, %2;" : "=r"(bb2[i]) : "f"(bhi), "f"(blo));
    }
    #pragma unroll
    for (int i = 0; i < 8; i++) ww[i] = __ldg(W2 + lane * 8 + i);
    float bias2 = __ldg(b2);

    const __nv_bfloat16* P = g_P;
    for (int e = gwarp; e < E; e += 2 * nwarps) {
        int e2 = e + nwarps;
        bool have2 = e2 < E;
        int s0 = src[e], d0 = dst[e];
        int s1 = have2 ? src[e2] : 0;
        int d1 = have2 ? dst[e2] : 0;

        uint4 u0 = *(const uint4*)(P + (size_t)s0 * NCOLS + lane * 8);
        uint4 v0 = *(const uint4*)(P + (size_t)d0 * NCOLS + DFEAT + lane * 8);
        uint4 u1 = *(const uint4*)(P + (size_t)s1 * NCOLS + lane * 8);
        uint4 v1 = *(const uint4*)(P + (size_t)d1 * NCOLS + DFEAT + lane * 8);

        float a0 = edge_dot2(u0, v0, bb2, ww);
        float a1 = edge_dot2(u1, v1, bb2, ww);
        #pragma unroll
        for (int o = 16; o; o >>= 1) {
            a0 += __shfl_xor_sync(0xffffffffu, a0, o);
            a1 += __shfl_xor_sync(0xffffffffu, a1, o);
        }
        if (lane == 0) {
            out[e] = 1.f / (1.f + __expf(-(a0 + bias2)));
            if (have2) out[e2] = 1.f / (1.f + __expf(-(a1 + bias2)));
        }
    }
}

extern "C" void kernel_launch(void* const* d_in, const int* in_sizes, int n_in,
                              void* d_out, int out_size) {
    const float* h   = (const float*)d_in[0];
    const int*   src = (const int*)d_in[1];
    const int*   dst = (const int*)d_in[2];
    const float* W1  = (const float*)d_in[3];
    const float* b1  = (const float*)d_in[4];
    const float* W2  = (const float*)d_in[5];
    const float* b2  = (const float*)d_in[6];
    float* out = (float*)d_out;

    int M = in_sizes[0] / DFEAT;
    int E = in_sizes[1];

    prep_w<<<(NCOLS * DFEAT + 255) / 256, 256>>>(W1);
    {
        int n8 = M * DFEAT / 8;
        prep_h<<<(n8 + 255) / 256, 256>>>(h, M);
    }

    cudaFuncSetAttribute(gemm_bf16, cudaFuncAttributeMaxDynamicSharedMemorySize,
                         SMEM_BYTES);
    dim3 gg(NCOLS / BN, (M + BM - 1) / BM);   // x-fastest => A reuse in L2
    gemm_bf16<<<gg, 256, SMEM_BYTES>>>(M);

    edge_mlp<<<2368, 256>>>(src, dst, b1, W2, b2, out, E);
}

// round 14
// speedup vs baseline: 1.3062x; 1.3062x over previous
#include <cuda_runtime.h>
#include <cuda_bf16.h>
#include <cstdint>

#define DFEAT 256
#define NCOLS 512
#define MAXN  100000

// Scratch: P = [u | v+b1] per node, bf16, 16B-aligned (uint4 reads).
// g_Hb = h converted to bf16 [M x 256]. g_W2 = W1 rearranged, k-pair interleaved.
__device__ __align__(16) __nv_bfloat16 g_P[(size_t)MAXN * NCOLS];
__device__ __align__(16) __nv_bfloat16 g_Hb[(size_t)MAXN * DFEAT];
__device__ __align__(16) __nv_bfloat16 g_W2[(DFEAT / 2) * NCOLS * 2];

// Wcat[k][j] = W1[k][j] (j<256) | W1[256+k][j-256]; stored pair-interleaved bf16.
__global__ void prep_w(const float* __restrict__ W1) {
    int idx = blockIdx.x * blockDim.x + threadIdx.x;
    if (idx >= NCOLS * DFEAT) return;
    int j = idx >> 8;          // output col 0..511
    int k = idx & 255;         // input  dim 0..255
    float w = (j < DFEAT) ? W1[k * DFEAT + j]
                          : W1[(DFEAT + k) * DFEAT + (j - DFEAT)];
    g_W2[(size_t)(k >> 1) * (NCOLS * 2) + j * 2 + (k & 1)] = __float2bfloat16(w);
}

// h (fp32) -> g_Hb (bf16), 8 elements per thread, pure streaming.
__global__ void prep_h(const float* __restrict__ h, int M) {
    size_t i8 = (size_t)(blockIdx.x * blockDim.x + threadIdx.x);
    size_t total = (size_t)M * DFEAT / 8;
    if (i8 >= total) return;
    const float4* src = (const float4*)h + i8 * 2;
    float4 f0 = src[0], f1 = src[1];
    uint4 o;
    asm("cvt.rn.bf16x2.f32 %0, %1, %2;" : "=r"(o.x) : "f"(f0.y), "f"(f0.x));
    asm("cvt.rn.bf16x2.f32 %0, %1, %2;" : "=r"(o.y) : "f"(f0.w), "f"(f0.z));
    asm("cvt.rn.bf16x2.f32 %0, %1, %2;" : "=r"(o.z) : "f"(f1.y), "f"(f1.x));
    asm("cvt.rn.bf16x2.f32 %0, %1, %2;" : "=r"(o.w) : "f"(f1.w), "f"(f1.z));
    ((uint4*)g_Hb)[i8] = o;
}

// ----- bf16 m16n8k16 GEMM, 3-stage cp.async, 2 CTAs/SM, bf16 A path (R12) -----
#define BM 128
#define BN 128
#define BK 32
#define ABST 40                    // A row stride in bf16 (80B) - conflict-free LDS.32
#define BSTR2 136                  // B row stride in uint32 (544B)
#define A_STAGE_H (BM * ABST)      // bf16 units per A stage
#define B_STAGE (BK / 2 * BSTR2)   // uint32 words per B stage
#define NSTAGE 3
#define SMEM_BYTES (NSTAGE * (A_STAGE_H * 2 + B_STAGE * 4))   // 56832 B

__device__ __forceinline__ void cp16(void* dst_s, const void* src_g, bool pred) {
    uint32_t d = (uint32_t)__cvta_generic_to_shared(dst_s);
    int sz = pred ? 16 : 0;   // 0 => zero-fill
    asm volatile("cp.async.ca.shared.global [%0], [%1], 16, %2;"
                 :: "r"(d), "l"(src_g), "r"(sz));
}

__global__ __launch_bounds__(256, 2) void gemm_bf16(int M, const float* __restrict__ b1) {
    extern __shared__ __align__(16) char smem[];
    __nv_bfloat16* As = (__nv_bfloat16*)smem;                      // [NSTAGE][A_STAGE_H]
    uint32_t*      Bs = (uint32_t*)(smem + NSTAGE * A_STAGE_H * 2);// [NSTAGE][B_STAGE]

    int tid  = threadIdx.x;
    int lane = tid & 31, warp = tid >> 5;
    int wm = (warp >> 2) * 64;         // warp grid 2(m) x 4(n), warp tile 64x32
    int wn = (warp & 3) * 32;
    int g  = lane >> 2, tg = lane & 3;
    int rowBase = blockIdx.y * BM;
    int nBase   = blockIdx.x * BN;

    float c[4][4][4];
    #pragma unroll
    for (int i = 0; i < 4; i++)
        #pragma unroll
        for (int j = 0; j < 4; j++)
            #pragma unroll
            for (int q = 0; q < 4; q++) c[i][j][q] = 0.f;

    // A-load mapping: 128 rows x 64B = 512 x 16B slots, 2/thread
    int ar[2], ac[2];
    #pragma unroll
    for (int i = 0; i < 2; i++) {
        int idx = tid + 256 * i;
        ar[i] = idx >> 2;           // row 0..127
        ac[i] = (idx & 3) << 3;     // col 0..24 step 8 (bf16 units)
    }
    // B-load mapping: 512 x 16B slots, 2/thread (16 rows x 128 uint32)
    int br[2], bc[2];
    #pragma unroll
    for (int i = 0; i < 2; i++) {
        int idx = tid + 256 * i;
        br[i] = idx >> 5;           // k2 row 0..15
        bc[i] = (idx & 31) << 2;    // word col 0..124 step 4
    }

    auto load_stage = [&](int st, int k0) {
        __nv_bfloat16* a_s = As + st * A_STAGE_H;
        uint32_t*      b_s = Bs + st * B_STAGE;
        #pragma unroll
        for (int i = 0; i < 2; i++) {
            int grow = rowBase + ar[i];
            cp16(a_s + ar[i] * ABST + ac[i],
                 g_Hb + (size_t)grow * DFEAT + k0 + ac[i], grow < M);
        }
        int k2base = k0 >> 1;
        #pragma unroll
        for (int i = 0; i < 2; i++) {
            cp16(b_s + br[i] * BSTR2 + bc[i],
                 g_W2 + (size_t)(k2base + br[i]) * (NCOLS * 2) + nBase * 2 + bc[i] * 2,
                 true);
        }
        asm volatile("cp.async.commit_group;");
    };

    load_stage(0, 0);
    load_stage(1, BK);

    for (int ck = 0; ck < DFEAT / BK; ck++) {          // 8 chunks
        if (ck + 1 < DFEAT / BK) asm volatile("cp.async.wait_group 1;");
        else                     asm volatile("cp.async.wait_group 0;");
        __syncthreads();

        const __nv_bfloat16* a_s = As + (ck % NSTAGE) * A_STAGE_H;
        const uint32_t*      b_s = Bs + (ck % NSTAGE) * B_STAGE;

        #pragma unroll
        for (int kk = 0; kk < BK; kk += 16) {
            // A frags (m16n8k16): a0 (g,2tg) a1 (g+8,2tg) a2 (g,2tg+8) a3 (g+8,2tg+8)
            uint32_t a[4][4];
            #pragma unroll
            for (int mt = 0; mt < 4; mt++) {
                const __nv_bfloat16* ap = a_s + (wm + mt * 16) * ABST + kk + 2 * tg;
                a[mt][0] = *(const uint32_t*)(ap + g * ABST);
                a[mt][1] = *(const uint32_t*)(ap + (g + 8) * ABST);
                a[mt][2] = *(const uint32_t*)(ap + g * ABST + 8);
                a[mt][3] = *(const uint32_t*)(ap + (g + 8) * ABST + 8);
            }
            // B frags: b0 = pair row (kk/2 + tg), b1 = pair row (kk/2 + tg + 4), col n
            uint32_t b[4][2];
            #pragma unroll
            for (int nt = 0; nt < 4; nt++) {
                const uint32_t* bp = b_s + (kk >> 1) * BSTR2 + wn + nt * 8 + g;
                b[nt][0] = bp[tg * BSTR2];
                b[nt][1] = bp[(tg + 4) * BSTR2];
            }
            #pragma unroll
            for (int mt = 0; mt < 4; mt++)
                #pragma unroll
                for (int nt = 0; nt < 4; nt++) {
                    asm volatile(
                        "mma.sync.aligned.m16n8k16.row.col.f32.bf16.bf16.f32 "
                        "{%0,%1,%2,%3}, {%4,%5,%6,%7}, {%8,%9}, {%0,%1,%2,%3};"
                        : "+f"(c[mt][nt][0]), "+f"(c[mt][nt][1]),
                          "+f"(c[mt][nt][2]), "+f"(c[mt][nt][3])
                        : "r"(a[mt][0]), "r"(a[mt][1]), "r"(a[mt][2]), "r"(a[mt][3]),
                          "r"(b[nt][0]), "r"(b[nt][1]));
                }
        }
        __syncthreads();

        if (ck + 2 < DFEAT / BK) load_stage((ck + 2) % NSTAGE, (ck + 2) * BK);
    }

    // Epilogue -> bf16 P, folding b1 into the v-half (cols >= 256) in fp32.
    // C frag: c0 (g,2tg) c1 (g,2tg+1) c2 (g+8,2tg) c3 (g+8,2tg+1)
    bool vhalf = (nBase >= DFEAT);
    #pragma unroll
    for (int mt = 0; mt < 4; mt++) {
        int row0 = rowBase + wm + mt * 16 + g;
        #pragma unroll
        for (int nt = 0; nt < 4; nt++) {
            int col = nBase + wn + nt * 8 + 2 * tg;
            float add0 = 0.f, add1 = 0.f;
            if (vhalf) {
                add0 = __ldg(b1 + col - DFEAT);
                add1 = __ldg(b1 + col + 1 - DFEAT);
            }
            if (row0 < M)
                *(__nv_bfloat162*)(g_P + (size_t)row0 * NCOLS + col) =
                    __float22bfloat162_rn(make_float2(c[mt][nt][0] + add0,
                                                      c[mt][nt][1] + add1));
            if (row0 + 8 < M)
                *(__nv_bfloat162*)(g_P + (size_t)(row0 + 8) * NCOLS + col) =
                    __float22bfloat162_rn(make_float2(c[mt][nt][2] + add0,
                                                      c[mt][nt][3] + add1));
        }
    }
}

// ------------- edge pass (R12 structure, bias removed): warp/edge, 2 deep ----
__device__ __forceinline__ float edge_dot(uint4 uu, uint4 vv, const float* ww) {
    float acc = 0.f;
    const uint32_t* up = &uu.x;
    const uint32_t* vp = &vv.x;
    #pragma unroll
    for (int q = 0; q < 4; q++) {
        float2 uf = __bfloat1622float2(*(const __nv_bfloat162*)&up[q]);
        float2 vf = __bfloat1622float2(*(const __nv_bfloat162*)&vp[q]);
        float t;
        t = uf.x + vf.x; if (t > 0.f) acc += t * ww[2 * q];
        t = uf.y + vf.y; if (t > 0.f) acc += t * ww[2 * q + 1];
    }
    return acc;
}

__global__ __launch_bounds__(256) void edge_mlp(
        const int* __restrict__ src, const int* __restrict__ dst,
        const float* __restrict__ W2,
        const float* __restrict__ b2, float* __restrict__ out, int E) {
    int tid = threadIdx.x;
    int lane = tid & 31;
    int gwarp = blockIdx.x * 8 + (tid >> 5);
    int nwarps = gridDim.x * 8;

    float ww[8];
    #pragma unroll
    for (int i = 0; i < 8; i++) ww[i] = __ldg(W2 + lane * 8 + i);
    float bias2 = __ldg(b2);

    const __nv_bfloat16* P = g_P;
    for (int e = gwarp; e < E; e += 2 * nwarps) {
        int e2 = e + nwarps;
        bool have2 = e2 < E;
        int s0 = src[e], d0 = dst[e];
        int s1 = have2 ? src[e2] : 0;
        int d1 = have2 ? dst[e2] : 0;

        uint4 u0 = *(const uint4*)(P + (size_t)s0 * NCOLS + lane * 8);
        uint4 v0 = *(const uint4*)(P + (size_t)d0 * NCOLS + DFEAT + lane * 8);
        uint4 u1 = *(const uint4*)(P + (size_t)s1 * NCOLS + lane * 8);
        uint4 v1 = *(const uint4*)(P + (size_t)d1 * NCOLS + DFEAT + lane * 8);

        float a0 = edge_dot(u0, v0, ww);
        float a1 = edge_dot(u1, v1, ww);
        #pragma unroll
        for (int o = 16; o; o >>= 1) {
            a0 += __shfl_xor_sync(0xffffffffu, a0, o);
            a1 += __shfl_xor_sync(0xffffffffu, a1, o);
        }
        if (lane == 0) {
            out[e] = 1.f / (1.f + __expf(-(a0 + bias2)));
            if (have2) out[e2] = 1.f / (1.f + __expf(-(a1 + bias2)));
        }
    }
}

extern "C" void kernel_launch(void* const* d_in, const int* in_sizes, int n_in,
                              void* d_out, int out_size) {
    const float* h   = (const float*)d_in[0];
    const int*   src = (const int*)d_in[1];
    const int*   dst = (const int*)d_in[2];
    const float* W1  = (const float*)d_in[3];
    const float* b1  = (const float*)d_in[4];
    const float* W2  = (const float*)d_in[5];
    const float* b2  = (const float*)d_in[6];
    float* out = (float*)d_out;

    int M = in_sizes[0] / DFEAT;
    int E = in_sizes[1];

    prep_w<<<(NCOLS * DFEAT + 255) / 256, 256>>>(W1);
    {
        int n8 = M * DFEAT / 8;
        prep_h<<<(n8 + 255) / 256, 256>>>(h, M);
    }

    cudaFuncSetAttribute(gemm_bf16, cudaFuncAttributeMaxDynamicSharedMemorySize,
                         SMEM_BYTES);
    dim3 gg(NCOLS / BN, (M + BM - 1) / BM);   // x-fastest => A reuse in L2
    gemm_bf16<<<gg, 256, SMEM_BYTES>>>(M, b1);

    edge_mlp<<<2368, 256>>>(src, dst, W2, b2, out, E);
}

// round 15
// speedup vs baseline: 1.3701x; 1.0489x over previous
#include <cuda_runtime.h>
#include <cuda_bf16.h>
#include <cstdint>

#define DFEAT 256
#define NCOLS 512
#define MAXN  100000

// Scratch: P = [u | v+b1] per node, bf16, 16B-aligned (uint4 reads).
// g_Hb = h in bf16. g_W2 = W rearranged for LDS.128 fragment loads:
// bf16 index = (j*128 + chunk*16 + p)*2 + (k&1), p = 4*tg + s, k2local = tg + 4s.
__device__ __align__(16) __nv_bfloat16 g_P[(size_t)MAXN * NCOLS];
__device__ __align__(16) __nv_bfloat16 g_Hb[(size_t)MAXN * DFEAT];
__device__ __align__(16) __nv_bfloat16 g_W2[(size_t)NCOLS * DFEAT];

// Wcat[k][j] = W1[k][j] (j<256) | W1[256+k][j-256]; stored per the uint4 scheme.
__global__ void prep_w(const float* __restrict__ W1) {
    int idx = blockIdx.x * blockDim.x + threadIdx.x;
    if (idx >= NCOLS * DFEAT) return;
    int j = idx >> 8;          // output col 0..511
    int k = idx & 255;         // input  dim 0..255
    float w = (j < DFEAT) ? W1[k * DFEAT + j]
                          : W1[(DFEAT + k) * DFEAT + (j - DFEAT)];
    int k2  = k >> 1;          // 0..127
    int c   = k2 >> 4;         // chunk 0..7
    int k2l = k2 & 15;
    int tg  = k2l & 3;
    int s   = k2l >> 2;
    int p   = tg * 4 + s;
    g_W2[((size_t)j * 128 + c * 16 + p) * 2 + (k & 1)] = __float2bfloat16(w);
}

// h (fp32) -> g_Hb (bf16), 8 elements per thread, pure streaming.
__global__ void prep_h(const float* __restrict__ h, int M) {
    size_t i8 = (size_t)(blockIdx.x * blockDim.x + threadIdx.x);
    size_t total = (size_t)M * DFEAT / 8;
    if (i8 >= total) return;
    const float4* src = (const float4*)h + i8 * 2;
    float4 f0 = src[0], f1 = src[1];
    uint4 o;
    asm("cvt.rn.bf16x2.f32 %0, %1, %2;" : "=r"(o.x) : "f"(f0.y), "f"(f0.x));
    asm("cvt.rn.bf16x2.f32 %0, %1, %2;" : "=r"(o.y) : "f"(f0.w), "f"(f0.z));
    asm("cvt.rn.bf16x2.f32 %0, %1, %2;" : "=r"(o.z) : "f"(f1.y), "f"(f1.x));
    asm("cvt.rn.bf16x2.f32 %0, %1, %2;" : "=r"(o.w) : "f"(f1.w), "f"(f1.z));
    ((uint4*)g_Hb)[i8] = o;
}

// ----- bf16 m16n8k16 GEMM: ldmatrix A + LDS.128 B, 3-stage cp.async ---------
#define BM 128
#define BN 128
#define BK 32
#define ABST 40                    // A row stride in bf16 (80B) - ldmatrix conflict-free
#define A_STAGE_H (BM * ABST)      // bf16 units per A stage (10240 B)
#define B_STAGE 2048               // uint32 words per B stage: 128 n x 16 words (8192 B)
#define NSTAGE 3
#define SMEM_BYTES (NSTAGE * (A_STAGE_H * 2 + B_STAGE * 4))   // 55296 B

__device__ __forceinline__ void cp16(void* dst_s, const void* src_g, bool pred) {
    uint32_t d = (uint32_t)__cvta_generic_to_shared(dst_s);
    int sz = pred ? 16 : 0;   // 0 => zero-fill
    asm volatile("cp.async.ca.shared.global [%0], [%1], 16, %2;"
                 :: "r"(d), "l"(src_g), "r"(sz));
}

__global__ __launch_bounds__(256, 2) void gemm_bf16(int M, const float* __restrict__ b1) {
    extern __shared__ __align__(16) char smem[];
    __nv_bfloat16* As = (__nv_bfloat16*)smem;                      // [NSTAGE][A_STAGE_H]
    uint32_t*      Bs = (uint32_t*)(smem + NSTAGE * A_STAGE_H * 2);// [NSTAGE][B_STAGE]

    int tid  = threadIdx.x;
    int lane = tid & 31, warp = tid >> 5;
    int wm = (warp >> 2) * 64;         // warp grid 2(m) x 4(n), warp tile 64x32
    int wn = (warp & 3) * 32;
    int g  = lane >> 2, tg = lane & 3;
    int rowBase = blockIdx.y * BM;
    int nBase   = blockIdx.x * BN;

    // ldmatrix lane mapping: rows (lane&15), col +8 for lanes 16-31
    int lrow = lane & 15;
    int lcol = (lane >> 4) << 3;

    float c[4][4][4];
    #pragma unroll
    for (int i = 0; i < 4; i++)
        #pragma unroll
        for (int j = 0; j < 4; j++)
            #pragma unroll
            for (int q = 0; q < 4; q++) c[i][j][q] = 0.f;

    // A-load mapping: 128 rows x 64B = 512 x 16B slots, 2/thread
    int ar[2], ac[2];
    #pragma unroll
    for (int i = 0; i < 2; i++) {
        int idx = tid + 256 * i;
        ar[i] = idx >> 2;           // row 0..127
        ac[i] = (idx & 3) << 3;     // col 0..24 step 8 (bf16 units)
    }
    // B-load mapping: 512 x 16B slots, 2/thread; slot -> (n = slot>>2, w4 = slot&3)
    int bn[2], bw[2];
    #pragma unroll
    for (int i = 0; i < 2; i++) {
        int idx = tid + 256 * i;
        bn[i] = idx >> 2;           // n row 0..127
        bw[i] = (idx & 3) << 2;     // word col 0,4,8,12
    }

    auto load_stage = [&](int st, int ckk) {
        __nv_bfloat16* a_s = As + st * A_STAGE_H;
        uint32_t*      b_s = Bs + st * B_STAGE;
        int k0 = ckk * BK;
        #pragma unroll
        for (int i = 0; i < 2; i++) {
            int grow = rowBase + ar[i];
            cp16(a_s + ar[i] * ABST + ac[i],
                 g_Hb + (size_t)grow * DFEAT + k0 + ac[i], grow < M);
        }
        #pragma unroll
        for (int i = 0; i < 2; i++) {
            cp16(b_s + bn[i] * 16 + bw[i],
                 g_W2 + ((size_t)(nBase + bn[i]) * 128 + ckk * 16 + bw[i]) * 2,
                 true);
        }
        asm volatile("cp.async.commit_group;");
    };

    load_stage(0, 0);
    load_stage(1, 1);

    for (int ck = 0; ck < DFEAT / BK; ck++) {          // 8 chunks
        if (ck + 1 < DFEAT / BK) asm volatile("cp.async.wait_group 1;");
        else                     asm volatile("cp.async.wait_group 0;");
        __syncthreads();

        const __nv_bfloat16* a_s = As + (ck % NSTAGE) * A_STAGE_H;
        const uint32_t*      b_s = Bs + (ck % NSTAGE) * B_STAGE;

        // B: one LDS.128 per nt covers b0/b1 for BOTH k-steps of this chunk.
        uint4 b4[4];
        #pragma unroll
        for (int nt = 0; nt < 4; nt++)
            b4[nt] = *(const uint4*)(b_s + (wn + nt * 8 + g) * 16 + 4 * tg);

        #pragma unroll
        for (int kh = 0; kh < 2; kh++) {               // kk = 0, 16
            int kk = kh << 4;
            // A frags via ldmatrix.x4: r0..r3 == a0..a3 of m16n8k16
            uint32_t a[4][4];
            #pragma unroll
            for (int mt = 0; mt < 4; mt++) {
                uint32_t addr = (uint32_t)__cvta_generic_to_shared(
                    a_s + (wm + mt * 16 + lrow) * ABST + kk + lcol);
                asm volatile(
                    "ldmatrix.sync.aligned.m8n8.x4.shared.b16 {%0,%1,%2,%3}, [%4];"
                    : "=r"(a[mt][0]), "=r"(a[mt][1]), "=r"(a[mt][2]), "=r"(a[mt][3])
                    : "r"(addr));
            }
            #pragma unroll
            for (int mt = 0; mt < 4; mt++)
                #pragma unroll
                for (int nt = 0; nt < 4; nt++) {
                    uint32_t b0 = kh ? b4[nt].z : b4[nt].x;
                    uint32_t b1r = kh ? b4[nt].w : b4[nt].y;
                    asm volatile(
                        "mma.sync.aligned.m16n8k16.row.col.f32.bf16.bf16.f32 "
                        "{%0,%1,%2,%3}, {%4,%5,%6,%7}, {%8,%9}, {%0,%1,%2,%3};"
                        : "+f"(c[mt][nt][0]), "+f"(c[mt][nt][1]),
                          "+f"(c[mt][nt][2]), "+f"(c[mt][nt][3])
                        : "r"(a[mt][0]), "r"(a[mt][1]), "r"(a[mt][2]), "r"(a[mt][3]),
                          "r"(b0), "r"(b1r));
                }
        }
        __syncthreads();

        if (ck + 2 < DFEAT / BK) load_stage((ck + 2) % NSTAGE, ck + 2);
    }

    // Epilogue -> bf16 P, folding b1 into the v-half (cols >= 256) in fp32.
    bool vhalf = (nBase >= DFEAT);
    #pragma unroll
    for (int mt = 0; mt < 4; mt++) {
        int row0 = rowBase + wm + mt * 16 + g;
        #pragma unroll
        for (int nt = 0; nt < 4; nt++) {
            int col = nBase + wn + nt * 8 + 2 * tg;
            float add0 = 0.f, add1 = 0.f;
            if (vhalf) {
                add0 = __ldg(b1 + col - DFEAT);
                add1 = __ldg(b1 + col + 1 - DFEAT);
            }
            if (row0 < M)
                *(__nv_bfloat162*)(g_P + (size_t)row0 * NCOLS + col) =
                    __float22bfloat162_rn(make_float2(c[mt][nt][0] + add0,
                                                      c[mt][nt][1] + add1));
            if (row0 + 8 < M)
                *(__nv_bfloat162*)(g_P + (size_t)(row0 + 8) * NCOLS + col) =
                    __float22bfloat162_rn(make_float2(c[mt][nt][2] + add0,
                                                      c[mt][nt][3] + add1));
        }
    }
}

// ------------- edge pass (R14 verbatim, frozen): warp/edge, 2 deep ----------
__device__ __forceinline__ float edge_dot(uint4 uu, uint4 vv, const float* ww) {
    float acc = 0.f;
    const uint32_t* up = &uu.x;
    const uint32_t* vp = &vv.x;
    #pragma unroll
    for (int q = 0; q < 4; q++) {
        float2 uf = __bfloat1622float2(*(const __nv_bfloat162*)&up[q]);
        float2 vf = __bfloat1622float2(*(const __nv_bfloat162*)&vp[q]);
        float t;
        t = uf.x + vf.x; if (t > 0.f) acc += t * ww[2 * q];
        t = uf.y + vf.y; if (t > 0.f) acc += t * ww[2 * q + 1];
    }
    return acc;
}

__global__ __launch_bounds__(256) void edge_mlp(
        const int* __restrict__ src, const int* __restrict__ dst,
        const float* __restrict__ W2,
        const float* __restrict__ b2, float* __restrict__ out, int E) {
    int tid = threadIdx.x;
    int lane = tid & 31;
    int gwarp = blockIdx.x * 8 + (tid >> 5);
    int nwarps = gridDim.x * 8;

    float ww[8];
    #pragma unroll
    for (int i = 0; i < 8; i++) ww[i] = __ldg(W2 + lane * 8 + i);
    float bias2 = __ldg(b2);

    const __nv_bfloat16* P = g_P;
    for (int e = gwarp; e < E; e += 2 * nwarps) {
        int e2 = e + nwarps;
        bool have2 = e2 < E;
        int s0 = src[e], d0 = dst[e];
        int s1 = have2 ? src[e2] : 0;
        int d1 = have2 ? dst[e2] : 0;

        uint4 u0 = *(const uint4*)(P + (size_t)s0 * NCOLS + lane * 8);
        uint4 v0 = *(const uint4*)(P + (size_t)d0 * NCOLS + DFEAT + lane * 8);
        uint4 u1 = *(const uint4*)(P + (size_t)s1 * NCOLS + lane * 8);
        uint4 v1 = *(const uint4*)(P + (size_t)d1 * NCOLS + DFEAT + lane * 8);

        float a0 = edge_dot(u0, v0, ww);
        float a1 = edge_dot(u1, v1, ww);
        #pragma unroll
        for (int o = 16; o; o >>= 1) {
            a0 += __shfl_xor_sync(0xffffffffu, a0, o);
            a1 += __shfl_xor_sync(0xffffffffu, a1, o);
        }
        if (lane == 0) {
            out[e] = 1.f / (1.f + __expf(-(a0 + bias2)));
            if (have2) out[e2] = 1.f / (1.f + __expf(-(a1 + bias2)));
        }
    }
}

extern "C" void kernel_launch(void* const* d_in, const int* in_sizes, int n_in,
                              void* d_out, int out_size) {
    const float* h   = (const float*)d_in[0];
    const int*   src = (const int*)d_in[1];
    const int*   dst = (const int*)d_in[2];
    const float* W1  = (const float*)d_in[3];
    const float* b1  = (const float*)d_in[4];
    const float* W2  = (const float*)d_in[5];
    const float* b2  = (const float*)d_in[6];
    float* out = (float*)d_out;

    int M = in_sizes[0] / DFEAT;
    int E = in_sizes[1];

    prep_w<<<(NCOLS * DFEAT + 255) / 256, 256>>>(W1);
    {
        int n8 = M * DFEAT / 8;
        prep_h<<<(n8 + 255) / 256, 256>>>(h, M);
    }

    cudaFuncSetAttribute(gemm_bf16, cudaFuncAttributeMaxDynamicSharedMemorySize,
                         SMEM_BYTES);
    dim3 gg(NCOLS / BN, (M + BM - 1) / BM);   // x-fastest => A reuse in L2
    gemm_bf16<<<gg, 256, SMEM_BYTES>>>(M, b1);

    edge_mlp<<<2368, 256>>>(src, dst, W2, b2, out, E);
}

// round 17
// speedup vs baseline: 1.5016x; 1.0960x over previous
#include <cuda_runtime.h>
#include <cuda_bf16.h>
#include <cuda_fp16.h>
#include <cstdint>

#define DFEAT 256
#define NCOLS 512
#define MAXN  100000

// Scratch: P = [u | v+b1] per node in fp16, 16B-aligned (uint4 reads).
// g_Hb = h in bf16 (GEMM A). g_W2 = W rearranged for LDS.128 fragment loads.
__device__ __align__(16) __half        g_P[(size_t)MAXN * NCOLS];
__device__ __align__(16) __nv_bfloat16 g_Hb[(size_t)MAXN * DFEAT];
__device__ __align__(16) __nv_bfloat16 g_W2[(size_t)NCOLS * DFEAT];

// Wcat[k][j] = W1[k][j] (j<256) | W1[256+k][j-256]; uint4-fragment layout:
// bf16 index = (j*128 + chunk*16 + p)*2 + (k&1), p = 4*tg + s, k2local = tg + 4s.
__global__ void prep_w(const float* __restrict__ W1) {
    int idx = blockIdx.x * blockDim.x + threadIdx.x;
    if (idx >= NCOLS * DFEAT) return;
    int j = idx >> 8;          // output col 0..511
    int k = idx & 255;         // input  dim 0..255
    float w = (j < DFEAT) ? W1[k * DFEAT + j]
                          : W1[(DFEAT + k) * DFEAT + (j - DFEAT)];
    int k2  = k >> 1;
    int c   = k2 >> 4;
    int k2l = k2 & 15;
    int tg  = k2l & 3;
    int s   = k2l >> 2;
    int p   = tg * 4 + s;
    g_W2[((size_t)j * 128 + c * 16 + p) * 2 + (k & 1)] = __float2bfloat16(w);
}

// h (fp32) -> g_Hb (bf16), 8 elements per thread, pure streaming.
__global__ void prep_h(const float* __restrict__ h, int M) {
    size_t i8 = (size_t)(blockIdx.x * blockDim.x + threadIdx.x);
    size_t total = (size_t)M * DFEAT / 8;
    if (i8 >= total) return;
    const float4* src = (const float4*)h + i8 * 2;
    float4 f0 = src[0], f1 = src[1];
    uint4 o;
    asm("cvt.rn.bf16x2.f32 %0, %1, %2;" : "=r"(o.x) : "f"(f0.y), "f"(f0.x));
    asm("cvt.rn.bf16x2.f32 %0, %1, %2;" : "=r"(o.y) : "f"(f0.w), "f"(f0.z));
    asm("cvt.rn.bf16x2.f32 %0, %1, %2;" : "=r"(o.z) : "f"(f1.y), "f"(f1.x));
    asm("cvt.rn.bf16x2.f32 %0, %1, %2;" : "=r"(o.w) : "f"(f1.w), "f"(f1.z));
    ((uint4*)g_Hb)[i8] = o;
}

// ----- bf16 m16n8k16 GEMM: ldmatrix A + LDS.128 B, 3-stage cp.async (R15) ---
#define BM 128
#define BN 128
#define BK 32
#define ABST 40                    // A row stride in bf16 (80B) - ldmatrix conflict-free
#define A_STAGE_H (BM * ABST)      // bf16 units per A stage (10240 B)
#define B_STAGE 2048               // uint32 words per B stage (8192 B)
#define NSTAGE 3
#define SMEM_BYTES (NSTAGE * (A_STAGE_H * 2 + B_STAGE * 4))   // 55296 B

__device__ __forceinline__ void cp16(void* dst_s, const void* src_g, bool pred) {
    uint32_t d = (uint32_t)__cvta_generic_to_shared(dst_s);
    int sz = pred ? 16 : 0;   // 0 => zero-fill
    asm volatile("cp.async.ca.shared.global [%0], [%1], 16, %2;"
                 :: "r"(d), "l"(src_g), "r"(sz));
}

__global__ __launch_bounds__(256, 2) void gemm_bf16(int M, const float* __restrict__ b1) {
    extern __shared__ __align__(16) char smem[];
    __nv_bfloat16* As = (__nv_bfloat16*)smem;                      // [NSTAGE][A_STAGE_H]
    uint32_t*      Bs = (uint32_t*)(smem + NSTAGE * A_STAGE_H * 2);// [NSTAGE][B_STAGE]

    int tid  = threadIdx.x;
    int lane = tid & 31, warp = tid >> 5;
    int wm = (warp >> 2) * 64;         // warp grid 2(m) x 4(n), warp tile 64x32
    int wn = (warp & 3) * 32;
    int g  = lane >> 2, tg = lane & 3;
    int rowBase = blockIdx.y * BM;
    int nBase   = blockIdx.x * BN;

    int lrow = lane & 15;
    int lcol = (lane >> 4) << 3;

    float c[4][4][4];
    #pragma unroll
    for (int i = 0; i < 4; i++)
        #pragma unroll
        for (int j = 0; j < 4; j++)
            #pragma unroll
            for (int q = 0; q < 4; q++) c[i][j][q] = 0.f;

    int ar[2], ac[2];
    #pragma unroll
    for (int i = 0; i < 2; i++) {
        int idx = tid + 256 * i;
        ar[i] = idx >> 2;           // row 0..127
        ac[i] = (idx & 3) << 3;     // col 0..24 step 8 (bf16 units)
    }
    int bn[2], bw[2];
    #pragma unroll
    for (int i = 0; i < 2; i++) {
        int idx = tid + 256 * i;
        bn[i] = idx >> 2;           // n row 0..127
        bw[i] = (idx & 3) << 2;     // word col 0,4,8,12
    }

    auto load_stage = [&](int st, int ckk) {
        __nv_bfloat16* a_s = As + st * A_STAGE_H;
        uint32_t*      b_s = Bs + st * B_STAGE;
        int k0 = ckk * BK;
        #pragma unroll
        for (int i = 0; i < 2; i++) {
            int grow = rowBase + ar[i];
            cp16(a_s + ar[i] * ABST + ac[i],
                 g_Hb + (size_t)grow * DFEAT + k0 + ac[i], grow < M);
        }
        #pragma unroll
        for (int i = 0; i < 2; i++) {
            cp16(b_s + bn[i] * 16 + bw[i],
                 g_W2 + ((size_t)(nBase + bn[i]) * 128 + ckk * 16 + bw[i]) * 2,
                 true);
        }
        asm volatile("cp.async.commit_group;");
    };

    load_stage(0, 0);
    load_stage(1, 1);

    for (int ck = 0; ck < DFEAT / BK; ck++) {          // 8 chunks
        if (ck + 1 < DFEAT / BK) asm volatile("cp.async.wait_group 1;");
        else                     asm volatile("cp.async.wait_group 0;");
        __syncthreads();

        const __nv_bfloat16* a_s = As + (ck % NSTAGE) * A_STAGE_H;
        const uint32_t*      b_s = Bs + (ck % NSTAGE) * B_STAGE;

        uint4 b4[4];
        #pragma unroll
        for (int nt = 0; nt < 4; nt++)
            b4[nt] = *(const uint4*)(b_s + (wn + nt * 8 + g) * 16 + 4 * tg);

        #pragma unroll
        for (int kh = 0; kh < 2; kh++) {               // kk = 0, 16
            int kk = kh << 4;
            uint32_t a[4][4];
            #pragma unroll
            for (int mt = 0; mt < 4; mt++) {
                uint32_t addr = (uint32_t)__cvta_generic_to_shared(
                    a_s + (wm + mt * 16 + lrow) * ABST + kk + lcol);
                asm volatile(
                    "ldmatrix.sync.aligned.m8n8.x4.shared.b16 {%0,%1,%2,%3}, [%4];"
                    : "=r"(a[mt][0]), "=r"(a[mt][1]), "=r"(a[mt][2]), "=r"(a[mt][3])
                    : "r"(addr));
            }
            #pragma unroll
            for (int mt = 0; mt < 4; mt++)
                #pragma unroll
                for (int nt = 0; nt < 4; nt++) {
                    uint32_t b0 = kh ? b4[nt].z : b4[nt].x;
                    uint32_t b1r = kh ? b4[nt].w : b4[nt].y;
                    asm volatile(
                        "mma.sync.aligned.m16n8k16.row.col.f32.bf16.bf16.f32 "
                        "{%0,%1,%2,%3}, {%4,%5,%6,%7}, {%8,%9}, {%0,%1,%2,%3};"
                        : "+f"(c[mt][nt][0]), "+f"(c[mt][nt][1]),
                          "+f"(c[mt][nt][2]), "+f"(c[mt][nt][3])
                        : "r"(a[mt][0]), "r"(a[mt][1]), "r"(a[mt][2]), "r"(a[mt][3]),
                          "r"(b0), "r"(b1r));
                }
        }
        __syncthreads();

        if (ck + 2 < DFEAT / BK) load_stage((ck + 2) % NSTAGE, ck + 2);
    }

    // Epilogue -> fp16 P, folding b1 into the v-half (cols >= 256) in fp32.
    bool vhalf = (nBase >= DFEAT);
    #pragma unroll
    for (int mt = 0; mt < 4; mt++) {
        int row0 = rowBase + wm + mt * 16 + g;
        #pragma unroll
        for (int nt = 0; nt < 4; nt++) {
            int col = nBase + wn + nt * 8 + 2 * tg;
            float add0 = 0.f, add1 = 0.f;
            if (vhalf) {
                add0 = __ldg(b1 + col - DFEAT);
                add1 = __ldg(b1 + col + 1 - DFEAT);
            }
            if (row0 < M)
                *(__half2*)(g_P + (size_t)row0 * NCOLS + col) =
                    __floats2half2_rn(c[mt][nt][0] + add0, c[mt][nt][1] + add1);
            if (row0 + 8 < M)
                *(__half2*)(g_P + (size_t)(row0 + 8) * NCOLS + col) =
                    __floats2half2_rn(c[mt][nt][2] + add0, c[mt][nt][3] + add1);
        }
    }
}

// ------------- edge pass: warp/edge, 2 deep, packed half2 math ---------------
__device__ __forceinline__ float edge_dot_h2(uint4 uu, uint4 vv, const __half2* w2p) {
    const __half2* up = (const __half2*)&uu.x;
    const __half2* vp = (const __half2*)&vv.x;
    __half2 zero = __float2half2_rn(0.f);
    __half2 acc2 = zero;
    #pragma unroll
    for (int q = 0; q < 4; q++) {
        __half2 t = __hadd2(up[q], vp[q]);   // u + (v+b1)
        t = __hmax2(t, zero);                // relu
        acc2 = __hfma2(t, w2p[q], acc2);     // packed accumulate
    }
    float2 f = __half22float2(acc2);
    return f.x + f.y;
}

__global__ __launch_bounds__(256) void edge_mlp(
        const int* __restrict__ src, const int* __restrict__ dst,
        const float* __restrict__ W2,
        const float* __restrict__ b2, float* __restrict__ out, int E) {
    int tid = threadIdx.x;
    int lane = tid & 31;
    int gwarp = blockIdx.x * 8 + (tid >> 5);
    int nwarps = gridDim.x * 8;

    // per-lane W2 slice packed to half2
    __half2 w2p[4];
    #pragma unroll
    for (int i = 0; i < 4; i++) {
        float wlo = __ldg(W2 + lane * 8 + 2 * i);
        float whi = __ldg(W2 + lane * 8 + 2 * i + 1);
        w2p[i] = __floats2half2_rn(wlo, whi);
    }
    float bias2 = __ldg(b2);

    const __half* P = g_P;
    for (int e = gwarp; e < E; e += 2 * nwarps) {
        int e2 = e + nwarps;
        bool have2 = e2 < E;
        int s0 = src[e], d0 = dst[e];
        int s1 = have2 ? src[e2] : 0;
        int d1 = have2 ? dst[e2] : 0;

        uint4 u0 = *(const uint4*)(P + (size_t)s0 * NCOLS + lane * 8);
        uint4 v0 = *(const uint4*)(P + (size_t)d0 * NCOLS + DFEAT + lane * 8);
        uint4 u1 = *(const uint4*)(P + (size_t)s1 * NCOLS + lane * 8);
        uint4 v1 = *(const uint4*)(P + (size_t)d1 * NCOLS + DFEAT + lane * 8);

        float a0 = edge_dot_h2(u0, v0, w2p);
        float a1 = edge_dot_h2(u1, v1, w2p);
        #pragma unroll
        for (int o = 16; o; o >>= 1) {
            a0 += __shfl_xor_sync(0xffffffffu, a0, o);
            a1 += __shfl_xor_sync(0xffffffffu, a1, o);
        }
        if (lane == 0) {
            out[e] = 1.f / (1.f + __expf(-(a0 + bias2)));
            if (have2) out[e2] = 1.f / (1.f + __expf(-(a1 + bias2)));
        }
    }
}

extern "C" void kernel_launch(void* const* d_in, const int* in_sizes, int n_in,
                              void* d_out, int out_size) {
    const float* h   = (const float*)d_in[0];
    const int*   src = (const int*)d_in[1];
    const int*   dst = (const int*)d_in[2];
    const float* W1  = (const float*)d_in[3];
    const float* b1  = (const float*)d_in[4];
    const float* W2  = (const float*)d_in[5];
    const float* b2  = (const float*)d_in[6];
    float* out = (float*)d_out;

    int M = in_sizes[0] / DFEAT;
    int E = in_sizes[1];

    prep_w<<<(NCOLS * DFEAT + 255) / 256, 256>>>(W1);
    {
        int n8 = M * DFEAT / 8;
        prep_h<<<(n8 + 255) / 256, 256>>>(h, M);
    }

    cudaFuncSetAttribute(gemm_bf16, cudaFuncAttributeMaxDynamicSharedMemorySize,
                         SMEM_BYTES);
    dim3 gg(NCOLS / BN, (M + BM - 1) / BM);   // x-fastest => A reuse in L2
    gemm_bf16<<<gg, 256, SMEM_BYTES>>>(M, b1);

    edge_mlp<<<2368, 256>>>(src, dst, W2, b2, out, E);
}